// round 3
// baseline (speedup 1.0000x reference)
#include <cuda_runtime.h>
#include <math_constants.h>
#include <cstdint>

// RMAC: x [64,512,32,32] fp32 -> out [64,512,1,1]
// Row/col ranges (H=W=32, L=3): R0=[0,32) R1=[0,21) R2=[11,32) R3=[0,16) R4=[8,24) R5=[16,32)
// 14 regions: (R0,R0) w=2, 2x2 over {R1,R2}, 3x3 over {R3,R4,R5}.
// out[b,c] = sum_r w_r * M[b,r,c] / (sqrt(SS[b,r]) + 1e-6)

#define NREG   14
#define NCHUNK 8192      // 32768 maps / 4 maps per 16KB chunk
#define GRID1  592       // 4 blocks/SM x 148 SMs, fully resident

__device__ float g_M[64 * NREG * 512];   // region maxes
__device__ float g_SS[64 * NREG];        // sums of squares (atomic)

struct __align__(1024) Smem {
    float buf[2][4096];                  // 2 x 16KB chunk buffers (4 maps each)
    float s2[4][6][36];                  // per-warp col maxes (pad 36: f4-aligned, conflict-free)
    float ss[2][4][16];                  // per-iteration-parity per-warp region squares
    unsigned long long full[2];
    unsigned long long empty[2];
};

__device__ __forceinline__ uint32_t smem_u32(const void* p) {
    uint32_t a;
    asm("{ .reg .u64 t; cvta.to.shared.u64 t, %1; cvt.u32.u64 %0, t; }" : "=r"(a) : "l"(p));
    return a;
}
__device__ __forceinline__ void mbar_init(uint32_t a, uint32_t cnt) {
    asm volatile("mbarrier.init.shared.b64 [%0], %1;" :: "r"(a), "r"(cnt) : "memory");
}
__device__ __forceinline__ void mbar_expect_tx(uint32_t a, uint32_t bytes) {
    asm volatile("mbarrier.arrive.expect_tx.shared.b64 _, [%0], %1;" :: "r"(a), "r"(bytes) : "memory");
}
__device__ __forceinline__ void mbar_arrive(uint32_t a) {
    asm volatile("mbarrier.arrive.shared.b64 _, [%0];" :: "r"(a) : "memory");
}
__device__ __forceinline__ void mbar_wait(uint32_t a, uint32_t phase) {
    asm volatile(
        "{\n\t.reg .pred P;\n"
        "W%=:\n\t"
        "mbarrier.try_wait.parity.acquire.cta.shared::cta.b64 P, [%0], %1, 0x989680;\n\t"
        "@P bra D%=;\n\t"
        "bra W%=;\n"
        "D%=:\n\t}"
        :: "r"(a), "r"(phase) : "memory");
}
__device__ __forceinline__ void bulk_g2s(uint32_t dst, const void* src, uint32_t bytes, uint32_t mbar) {
    asm volatile(
        "cp.async.bulk.shared::cluster.global.mbarrier::complete_tx::bytes [%0], [%1], %2, [%3];"
        :: "r"(dst), "l"(src), "r"(bytes), "r"(mbar) : "memory");
}
__device__ __forceinline__ float4 f4max(float4 a, float4 b) {
    return make_float4(fmaxf(a.x, b.x), fmaxf(a.y, b.y), fmaxf(a.z, b.z), fmaxf(a.w, b.w));
}
__device__ __forceinline__ float4 shflx4(float4 v, int m) {
    float4 r;
    r.x = __shfl_xor_sync(0xffffffffu, v.x, m);
    r.y = __shfl_xor_sync(0xffffffffu, v.y, m);
    r.z = __shfl_xor_sync(0xffffffffu, v.z, m);
    r.w = __shfl_xor_sync(0xffffffffu, v.w, m);
    return r;
}

__global__ void zero_ss() {
    if (threadIdx.x < 64 * NREG) g_SS[threadIdx.x] = 0.0f;
}

__global__ __launch_bounds__(128) void rmac_stage1(const float* __restrict__ x) {
    __shared__ Smem sm;
    const int tid  = threadIdx.x;
    const int w    = tid >> 5;
    const int lane = tid & 31;
    const int q    = lane >> 3;   // row phase
    const int c0   = lane & 7;    // 4-col group

    const uint32_t fullA0  = smem_u32(&sm.full[0]),  fullA1  = smem_u32(&sm.full[1]);
    const uint32_t emptyA0 = smem_u32(&sm.empty[0]), emptyA1 = smem_u32(&sm.empty[1]);
    const uint32_t bufA0   = smem_u32(&sm.buf[0][0]), bufA1  = smem_u32(&sm.buf[1][0]);

    if (tid == 0) {
        mbar_init(fullA0, 1);    mbar_init(fullA1, 1);
        mbar_init(emptyA0, 128); mbar_init(emptyA1, 128);
    }
    __syncthreads();

    // prologue: prefetch first chunk into buffer 0
    if (tid == 0 && blockIdx.x < NCHUNK) {
        mbar_expect_tx(fullA0, 16384);
        bulk_g2s(bufA0, x + (size_t)blockIdx.x * 4096, 16384, fullA0);
    }

    int it = 0;
    for (int c = blockIdx.x; c < NCHUNK; c += GRID1, ++it) {
        const int s = it & 1;
        // prefetch next chunk into the other buffer
        if (tid == 0) {
            const int nc = c + GRID1;
            if (nc < NCHUNK) {
                const uint32_t emptyN = s ? emptyA0 : emptyA1;
                const uint32_t fullN  = s ? fullA0  : fullA1;
                const uint32_t bufN   = s ? bufA0   : bufA1;
                if (it >= 1) mbar_wait(emptyN, ((it - 1) >> 1) & 1);
                mbar_expect_tx(fullN, 16384);
                bulk_g2s(bufN, x + (size_t)nc * 4096, 16384, fullN);
            }
        }

        // wait for current chunk
        mbar_wait(s ? fullA1 : fullA0, (it >> 1) & 1);

        // this warp's map: rows 4k+q, cols 4c0..4c0+3 per float4 k
        const float4* __restrict__ p = (const float4*)(sm.buf[s]) + (w << 8) + lane;
        float4 v0 = p[0],   v1 = p[32],  v2 = p[64],  v3 = p[96];
        float4 v4 = p[128], v5 = p[160], v6 = p[192], v7 = p[224];

        float4 pc = f4max(v2, v3);                 // rows [8,16)
        float4 pd = f4max(v4, v5);                 // rows [16,24)
        float4 g3 = f4max(f4max(v0, v1), pc);      // rows [0,16)
        float4 g5 = f4max(pd, f4max(v6, v7));      // rows [16,32)
        float4 pb = (q == 3) ? pc : v3;            // rows [11,16)
        float4 pa = (q == 0) ? pd : v4;            // rows [16,21)

        float4 m0 = f4max(g3, g5);   // [0,32)
        float4 m1 = f4max(g3, pa);   // [0,21)
        float4 m2 = f4max(pb, g5);   // [11,32)
        float4 m3 = g3;              // [0,16)
        float4 m4 = f4max(pc, pd);   // [8,24)
        float4 m5 = g5;              // [16,32)

        // butterfly over row phase q (lanes +-8, +-16): full column maxes in all lanes
        m0 = f4max(m0, shflx4(m0, 8)); m0 = f4max(m0, shflx4(m0, 16));
        m1 = f4max(m1, shflx4(m1, 8)); m1 = f4max(m1, shflx4(m1, 16));
        m2 = f4max(m2, shflx4(m2, 8)); m2 = f4max(m2, shflx4(m2, 16));
        m3 = f4max(m3, shflx4(m3, 8)); m3 = f4max(m3, shflx4(m3, 16));
        m4 = f4max(m4, shflx4(m4, 8)); m4 = f4max(m4, shflx4(m4, 16));
        m5 = f4max(m5, shflx4(m5, 8)); m5 = f4max(m5, shflx4(m5, 16));

        if (q == 0) {   // lanes 0..7 publish col maxes (c0 == lane)
            *(float4*)&sm.s2[w][0][c0 << 2] = m0;
            *(float4*)&sm.s2[w][1][c0 << 2] = m1;
            *(float4*)&sm.s2[w][2][c0 << 2] = m2;
            *(float4*)&sm.s2[w][3][c0 << 2] = m3;
            *(float4*)&sm.s2[w][4][c0 << 2] = m4;
            *(float4*)&sm.s2[w][5][c0 << 2] = m5;
        }
        __syncwarp();

        const int map = (c << 2) + w;
        const int b   = map >> 9;
        const int ch  = map & 511;

        if (lane < NREG) {
            int R, Cc;
            if (lane == 0)     { R = 0; Cc = 0; }
            else if (lane < 5) { R = 1 + ((lane - 1) >> 1); Cc = 1 + ((lane - 1) & 1); }
            else               { int t = lane - 5; R = 3 + t / 3; Cc = 3 + t % 3; }
            const int cs = (Cc == 2) ? 11 : (Cc == 4) ? 8 : (Cc == 5) ? 16 : 0;
            const int ce = (Cc == 1) ? 21 : (Cc == 3) ? 16 : (Cc == 4) ? 24 : 32;
            float mm = -CUDART_INF_F;
            for (int j = cs; j < ce; ++j)
                mm = fmaxf(mm, sm.s2[w][R][j]);
            g_M[(b * NREG + lane) * 512 + ch] = mm;
            sm.ss[s][w][lane] = mm * mm;
        }
        __syncthreads();

        if (tid < NREG) {   // warp 0: one atomic per (chunk, region)
            float t = sm.ss[s][0][tid] + sm.ss[s][1][tid] +
                      sm.ss[s][2][tid] + sm.ss[s][3][tid];
            atomicAdd(&g_SS[b * NREG + tid], t);
        }
        mbar_arrive(s ? emptyA1 : emptyA0);
    }
}

__global__ __launch_bounds__(512) void rmac_stage2(float* __restrict__ out) {
    const int b   = blockIdx.x;
    const int tid = threadIdx.x;     // channel
    __shared__ float s_inv[NREG];
    if (tid < NREG)
        s_inv[tid] = 1.0f / (sqrtf(g_SS[b * NREG + tid]) + 1e-6f);
    __syncthreads();

    const float* __restrict__ base = g_M + b * NREG * 512 + tid;
    float acc = 2.0f * base[0] * s_inv[0];     // (R0,R0) has weight 2
#pragma unroll
    for (int r = 1; r < NREG; ++r)
        acc += base[r * 512] * s_inv[r];
    out[b * 512 + tid] = acc;
}

extern "C" void kernel_launch(void* const* d_in, const int* in_sizes, int n_in,
                              void* d_out, int out_size) {
    const float* x = (const float*)d_in[0];
    float* out = (float*)d_out;

    zero_ss<<<1, 896>>>();
    rmac_stage1<<<GRID1, 128>>>(x);
    rmac_stage2<<<64, 512>>>(out);
}

// round 4
// speedup vs baseline: 1.0916x; 1.0916x over previous
#include <cuda_runtime.h>
#include <math_constants.h>

// RMAC: x [64,512,32,32] fp32 -> out [64,512,1,1]
// Row/col ranges (H=W=32, L=3): R0=[0,32) R1=[0,21) R2=[11,32) R3=[0,16) R4=[8,24) R5=[16,32)
// 14 regions: (R0,R0) w=2 (global + l=1), 2x2 over {R1,R2}, 3x3 over {R3,R4,R5}.
// out[b,c] = sum_r w_r * M[b,r,c] / (sqrt(SS[b,r]) + 1e-6)

#define NREG 14

// Transposed scratch: g_M[(b*512+ch)*16 + r]  (pad 14->16 for aligned 2-sector stores)
__device__ float g_M[64 * 512 * 16];
// Region sums-of-squares; zero-initialized at load, re-zeroed by stage2 each run.
__device__ float g_SS[64 * NREG];

__device__ __forceinline__ float4 f4max(float4 a, float4 b) {
    return make_float4(fmaxf(a.x, b.x), fmaxf(a.y, b.y), fmaxf(a.z, b.z), fmaxf(a.w, b.w));
}
__device__ __forceinline__ float4 shflx4(float4 v, int m) {
    float4 r;
    r.x = __shfl_xor_sync(0xffffffffu, v.x, m);
    r.y = __shfl_xor_sync(0xffffffffu, v.y, m);
    r.z = __shfl_xor_sync(0xffffffffu, v.z, m);
    r.w = __shfl_xor_sync(0xffffffffu, v.w, m);
    return r;
}

// Warp per (b,c) map. Lane l: q = l>>3 (row phase), c0 = l&7 (4-col group).
// float4 k covers row 4k+q, cols 4c0..4c0+3. 8x LDG.128, fully coalesced.
__global__ __launch_bounds__(128, 8) void rmac_stage1(const float* __restrict__ x) {
    const int w    = threadIdx.x >> 5;
    const int lane = threadIdx.x & 31;
    const int wid  = blockIdx.x * 4 + w;      // (b,c) map index
    const int q    = lane >> 3;
    const int c0   = lane & 7;

    const float4* __restrict__ p = (const float4*)x + (size_t)wid * 256 + lane;

    float4 v0 = __ldcs(p +   0), v1 = __ldcs(p +  32);
    float4 v2 = __ldcs(p +  64), v3 = __ldcs(p +  96);
    float4 v4 = __ldcs(p + 128), v5 = __ldcs(p + 160);
    float4 v6 = __ldcs(p + 192), v7 = __ldcs(p + 224);

    // Primitive row-group maxes over this lane's rows 4k+q:
    float4 pc = f4max(v2, v3);                 // rows [8,16)
    float4 pd = f4max(v4, v5);                 // rows [16,24)
    float4 g3 = f4max(f4max(v0, v1), pc);      // rows [0,16)
    float4 g5 = f4max(pd, f4max(v6, v7));      // rows [16,32)
    float4 pb = (q == 3) ? pc : v3;            // rows [11,16): row 11 = k2,q3
    float4 pa = (q == 0) ? pd : v4;            // rows [16,21): row 20 = k5,q0

    float4 m0 = f4max(g3, g5);   // [0,32)
    float4 m1 = f4max(g3, pa);   // [0,21)
    float4 m2 = f4max(pb, g5);   // [11,32)
    float4 m3 = g3;              // [0,16)
    float4 m4 = f4max(pc, pd);   // [8,24)
    float4 m5 = g5;              // [16,32)

    // Butterfly across row-phase q (lane bits 3,4): full column maxes everywhere.
    m0 = f4max(m0, shflx4(m0, 8)); m0 = f4max(m0, shflx4(m0, 16));
    m1 = f4max(m1, shflx4(m1, 8)); m1 = f4max(m1, shflx4(m1, 16));
    m2 = f4max(m2, shflx4(m2, 8)); m2 = f4max(m2, shflx4(m2, 16));
    m3 = f4max(m3, shflx4(m3, 8)); m3 = f4max(m3, shflx4(m3, 16));
    m4 = f4max(m4, shflx4(m4, 8)); m4 = f4max(m4, shflx4(m4, 16));
    m5 = f4max(m5, shflx4(m5, 8)); m5 = f4max(m5, shflx4(m5, 16));

    __shared__ float s2[4][6][36];   // [warp][range][col] (pad 36)
    __shared__ float ss[4][16];      // per-warp region squares

    if (q == 0) {   // lanes 0..7: c0 == lane
        *(float4*)&s2[w][0][c0 << 2] = m0;
        *(float4*)&s2[w][1][c0 << 2] = m1;
        *(float4*)&s2[w][2][c0 << 2] = m2;
        *(float4*)&s2[w][3][c0 << 2] = m3;
        *(float4*)&s2[w][4][c0 << 2] = m4;
        *(float4*)&s2[w][5][c0 << 2] = m5;
    }
    __syncwarp();

    if (lane < NREG) {
        int R, Cc;
        if (lane == 0)     { R = 0; Cc = 0; }
        else if (lane < 5) { R = 1 + ((lane - 1) >> 1); Cc = 1 + ((lane - 1) & 1); }
        else               { int t = lane - 5; R = 3 + t / 3; Cc = 3 + t % 3; }
        const int cs = (Cc == 2) ? 11 : (Cc == 4) ? 8 : (Cc == 5) ? 16 : 0;
        const int ce = (Cc == 1) ? 21 : (Cc == 3) ? 16 : (Cc == 4) ? 24 : 32;
        float mm = -CUDART_INF_F;
        for (int j = cs; j < ce; ++j)
            mm = fmaxf(mm, s2[w][R][j]);
        g_M[wid * 16 + lane] = mm;      // dense 2-sector store per warp
        ss[w][lane] = mm * mm;
    }
    __syncthreads();

    if (threadIdx.x < NREG) {   // one atomic per (block, region); all 4 maps same b
        const int b = blockIdx.x >> 7;   // 128 blocks per batch
        float t = ss[0][threadIdx.x] + ss[1][threadIdx.x] +
                  ss[2][threadIdx.x] + ss[3][threadIdx.x];
        atomicAdd(&g_SS[b * NREG + threadIdx.x], t);
    }
}

__global__ __launch_bounds__(512) void rmac_stage2(float* __restrict__ out) {
    const int b   = blockIdx.x;
    const int tid = threadIdx.x;     // channel

    __shared__ float s_inv[NREG];
    if (tid < NREG)
        s_inv[tid] = 1.0f / (sqrtf(g_SS[b * NREG + tid]) + 1e-6f);
    __syncthreads();
    if (tid < NREG)                  // restore zeros for the next graph replay
        g_SS[b * NREG + tid] = 0.0f;

    const float* __restrict__ base = g_M + ((size_t)(b * 512 + tid)) * 16;
    float acc = 2.0f * base[0] * s_inv[0];     // (R0,R0) weight 2
#pragma unroll
    for (int r = 1; r < NREG; ++r)
        acc += base[r] * s_inv[r];
    out[b * 512 + tid] = acc;
}

extern "C" void kernel_launch(void* const* d_in, const int* in_sizes, int n_in,
                              void* d_out, int out_size) {
    const float* x = (const float*)d_in[0];
    float* out = (float*)d_out;

    rmac_stage1<<<8192, 128>>>(x);   // warp per map, 8 blocks/SM resident
    rmac_stage2<<<64, 512>>>(out);
}